// round 14
// baseline (speedup 1.0000x reference)
#include <cuda_runtime.h>
#include <cuda_bf16.h>
#include <math.h>
#include <cstdint>

typedef unsigned int u32;
typedef unsigned long long ull;

#define NCTA 128
#define NTHR 320          // 8 compute + 1 W-producer + 1 A-producer warps
#define HS_  33554432ull
#define BH_  65536
// W-ring 3x32KB + A-ring 3x16KB + 32KB zbuf + barriers
#define SMEM_DYN 180352

__device__ __align__(16) u32 g_W[31457280];      // weight images, B-fragment order
__device__ __align__(16) u32 g_x[16777216];      // x images, A-fragment order
__device__ __align__(16) u32 g_hA[2][4][65536];  // h images [parity][layer]
__device__ unsigned g_sync[2];                   // [0]=count, [1]=generation

__device__ __forceinline__ u32 sm_u32(const void* p) {
    u32 a;
    asm("{.reg .u64 t; cvta.to.shared.u64 t, %1; cvt.u32.u64 %0, t;}" : "=r"(a) : "l"(p));
    return a;
}
__device__ __forceinline__ ull pol_evict_first() {
    ull p; asm("createpolicy.fractional.L2::evict_first.b64 %0, 1.0;" : "=l"(p)); return p;
}
__device__ __forceinline__ ull pol_evict_last() {
    ull p; asm("createpolicy.fractional.L2::evict_last.b64 %0, 1.0;" : "=l"(p)); return p;
}
__device__ __forceinline__ void bulk_cp_pol(u32 dst, const void* src, u32 bytes, u32 mbar, ull pol) {
    asm volatile("cp.async.bulk.shared::cluster.global.mbarrier::complete_tx::bytes.L2::cache_hint "
                 "[%0], [%1], %2, [%3], %4;"
                 :: "r"(dst), "l"(src), "r"(bytes), "r"(mbar), "l"(pol) : "memory");
}
__device__ __forceinline__ void mbar_init(u32 a, u32 c) {
    asm volatile("mbarrier.init.shared.b64 [%0], %1;" :: "r"(a), "r"(c) : "memory");
}
__device__ __forceinline__ void mbar_expect(u32 a, u32 tx) {
    asm volatile("mbarrier.arrive.expect_tx.shared.b64 _, [%0], %1;" :: "r"(a), "r"(tx) : "memory");
}
__device__ __forceinline__ void mbar_arrive(u32 a) {
    asm volatile("mbarrier.arrive.shared.b64 _, [%0];" :: "r"(a) : "memory");
}
__device__ __forceinline__ void mbar_wait(u32 a, u32 ph) {
    u32 done = 0;
    while (!done)
        asm volatile("{.reg .pred p; mbarrier.try_wait.parity.acquire.cta.shared::cta.b64 "
                     "p, [%1], %2, 0x989680; selp.b32 %0,1,0,p;}"
                     : "=r"(done) : "r"(a), "r"(ph) : "memory");
}
__device__ __forceinline__ void mma16816(float* c, const u32* a, const u32* b) {
    asm("mma.sync.aligned.m16n8k16.row.col.f32.bf16.bf16.f32 "
        "{%0,%1,%2,%3}, {%4,%5,%6,%7}, {%8,%9}, {%0,%1,%2,%3};"
        : "+f"(c[0]), "+f"(c[1]), "+f"(c[2]), "+f"(c[3])
        : "r"(a[0]), "r"(a[1]), "r"(a[2]), "r"(a[3]), "r"(b[0]), "r"(b[1]));
}
__device__ __forceinline__ u32 pack2(float v0, float v1, bool lo) {
    __nv_bfloat16 h0 = __float2bfloat16(v0), h1 = __float2bfloat16(v1);
    if (lo) {
        h0 = __float2bfloat16(v0 - __bfloat162float(h0));
        h1 = __float2bfloat16(v1 - __bfloat162float(h1));
    }
    u32 u0 = ((__nv_bfloat16_raw)h0).x, u1 = ((__nv_bfloat16_raw)h1).x;
    return u0 | (u1 << 16);
}
__device__ __forceinline__ float fsig(float x) {
    return __fdividef(1.f, 1.f + __expf(-x));
}
__device__ __forceinline__ float ftanh(float x) {
    const float e = __expf(-2.f * x);
    return __fdividef(1.f - e, 1.f + e);
}
#define CBAR() asm volatile("bar.sync 1, 256;" ::: "memory")
#define GEN()  (*(volatile unsigned*)&g_sync[1])

// grid barrier over compute warps only (t < 256); producers observe GEN().
__device__ __forceinline__ void grid_sync_c() {
    CBAR();
    if (threadIdx.x == 0) {
        __threadfence();
        unsigned gen = GEN();
        if (atomicAdd(&g_sync[0], 1u) == NCTA - 1u) {
            g_sync[0] = 0;
            __threadfence();
            GEN() = gen + 1u;
        } else {
            while (GEN() == gen) __nanosleep(32);
        }
        __threadfence();
    }
    CBAR();
}

// prep_x also zeroes g_hA and g_sync (replay-safe state reset; keeps launch
// count at exactly 3 kernels per kernel_launch call).
__global__ void __launch_bounds__(256) prep_x(const float* __restrict__ x)
{
    const int s = blockIdx.x >> 5, c = blockIdx.x & 31;
    const int t = threadIdx.x;
    if (t < 32) {
        ((u32*)g_hA)[blockIdx.x * 32 + t] = 0;   // 16384*32 = 524288 words
        if (blockIdx.x == 0 && t < 2) g_sync[t] = 0;
    }
    u32* dst = g_x + (size_t)blockIdx.x * 1024;
    #pragma unroll
    for (int q = 0; q < 4; q++) {
        const int gw = t + 256 * q;
        const int mt = gw >> 8, rem = gw & 255, hl = rem >> 7, w = rem & 127;
        const int lane = w >> 2, reg = w & 3;
        const int row = mt * 16 + (lane >> 2) + (reg & 1) * 8;
        const int k   = c * 16 + (lane & 3) * 2 + (reg >> 1) * 8;
        const float* p = x + (size_t)s * 32768 + row * 512 + k;
        dst[gw] = pack2(p[0], p[1], hl != 0);
    }
}

// W image: per chunk [nt 0..15][lane 0..31][slot 0..3], slot = {bh0,bh1,bl0,bl1}
__global__ void __launch_bounds__(256) prep_w(
    const float* __restrict__ Wx0, const float* __restrict__ Wh0,
    const float* __restrict__ Wxr, const float* __restrict__ Whr)
{
    const int b = blockIdx.x;
    int l, nblk, c;
    if (b < 3072) { l = 0; nblk = b / 96; c = b % 96; }
    else { int r = b - 3072; l = 1 + r / 4096; r %= 4096; nblk = r / 128; c = r % 128; }
    const int ntA = (l == 0) ? 32 : 64;
    const float* Wsrc; int kb;
    if (c < ntA) { Wsrc = (l == 0) ? Wx0 : Wxr + (size_t)(l - 1) * 4194304; kb = c * 16; }
    else         { Wsrc = (l == 0) ? Wh0 : Whr + (size_t)(l - 1) * 4194304; kb = (c - ntA) * 16; }
    u32* dst = g_W + (size_t)b * 2048;
    const int t = threadIdx.x;
    #pragma unroll
    for (int q = 0; q < 8; q++) {
        const int gw = t + 256 * q;
        const int nt = gw >> 7, rem = gw & 127, lane = rem >> 2, slot = rem & 3;
        const int hl = slot >> 1, reg = slot & 1;
        const int n = nt * 8 + (lane >> 2);
        const int zc = (n & 3) * 1024 + nblk * 32 + (n >> 2);
        const int k = kb + (lane & 3) * 2 + reg * 8;
        dst[gw] = pack2(Wsrc[(size_t)k * 4096 + zc], Wsrc[(size_t)(k + 1) * 4096 + zc], hl != 0);
    }
}

__global__ void __launch_bounds__(NTHR, 1)
lstm_persist(const float* __restrict__ b0, const float* __restrict__ br,
             float* __restrict__ out)
{
    extern __shared__ __align__(16) u32 sm[];
    // layout (u32): W-ring [0,24576), A-ring [24576,36864), zbuf [36864,45056)
    float* zbuf = (float*)(sm + 36864);
    const u32 smb = sm_u32(sm);
    const u32 mbFW = smb + 180224u, mbEW = smb + 180248u;
    const u32 mbFA = smb + 180272u, mbEA = smb + 180296u;

    const int layer = blockIdx.x >> 5, nblk = blockIdx.x & 31;
    const int t = threadIdx.x, lane = t & 31, wid = t >> 5;
    const int mp = wid & 1, nq = wid >> 1;       // warp tile: 2 m-tiles x 4 n-tiles
    const int gid = lane >> 2, tig = lane & 3;
    const int ntA = (layer == 0) ? 32 : 64;
    const int nst = (ntA + 64) >> 2;             // stages per wave: 24 or 32
    const size_t wbase = (layer == 0) ? (size_t)nblk * 96
                                      : 3072 + ((size_t)(layer - 1) * 32 + nblk) * 128;
    const float* bias = (layer == 0) ? b0 : br + (size_t)(layer - 1) * 4096;

    if (t == 0) {
        #pragma unroll
        for (int i = 0; i < 3; i++) {
            mbar_init(mbFW + 8 * i, 1); mbar_init(mbEW + 8 * i, 8);
            mbar_init(mbFA + 8 * i, 1); mbar_init(mbEA + 8 * i, 8);
        }
        asm volatile("fence.proxy.async;" ::: "memory");
    }
    __syncthreads();

    // epilogue ownership: 4 rows x 2 adjacent hcols (t < 256 only)
    const int hp = t & 15;
    const int rowBase = (t >> 4) * 4;
    const int hcol0 = nblk * 32 + hp * 2;
    float b42[2][4];
    #pragma unroll
    for (int cc = 0; cc < 2; cc++)
        #pragma unroll
        for (int g = 0; g < 4; g++)
            b42[cc][g] = __ldg(bias + g * 1024 + ((hcol0 + cc) & 1023));
    float creg[4][2];
    #pragma unroll
    for (int i = 0; i < 4; i++) { creg[i][0] = 0.f; creg[i][1] = 0.f; }

    const int kchunk = hcol0 >> 4;
    const int kl = hcol0 & 15;
    const int tigk = (kl >> 1) & 3, regk = kl >> 3;

    // ring cursors
    int pwst = 0, pwlap = 0;   // W-producer
    int past = 0, palap = 0;   // A-producer
    int cst = 0,  clap = 0;    // consumer

    for (int w = 0; w < 512 + 3; w++) {
        const int s = w - layer;
        if (s >= 0 && s < 512) {
            const int prPrev = (w & 1) ^ 1, prCur = w & 1;

            if (wid == 8) {
                // ---- W producer: free-running, ring-backpressured; evict_last ----
                if (lane == 0) {
                    const ull polW = pol_evict_last();
                    for (int i = 0; i < nst; i++) {
                        if (pwlap > 0) mbar_wait(mbEW + 8 * pwst, (u32)((pwlap - 1) & 1));
                        const u32 full = mbFW + 8 * pwst;
                        mbar_expect(full, 32768u);
                        #pragma unroll
                        for (int q = 0; q < 4; q++)
                            bulk_cp_pol(smb + (u32)pwst * 32768u + (u32)q * 8192u,
                                        g_W + (wbase + i * 4 + q) * 2048, 8192u, full, polW);
                        if (++pwst == 3) { pwst = 0; pwlap++; }
                    }
                }
            } else if (wid == 9) {
                // ---- A producer: gated by grid-barrier generation; evict_first ----
                if (lane == 0) {
                    const ull polA = pol_evict_first();
                    if (w >= 1) {
                        while (GEN() < (unsigned)w) __nanosleep(16);
                        __threadfence();
                    }
                    const u32* a0 = (layer == 0) ? g_x + (size_t)s * 32768
                                                 : &g_hA[prPrev][layer - 1][0];
                    const u32* a1 = &g_hA[prPrev][layer][0];
                    for (int i = 0; i < nst; i++) {
                        if (palap > 0) mbar_wait(mbEA + 8 * past, (u32)((palap - 1) & 1));
                        const u32 full = mbFA + 8 * past;
                        mbar_expect(full, 16384u);
                        #pragma unroll
                        for (int q = 0; q < 4; q++) {
                            const int c = i * 4 + q;
                            const u32* A = (c < ntA) ? a0 + (size_t)c * 1024
                                                     : a1 + (size_t)(c - ntA) * 1024;
                            bulk_cp_pol(smb + 98304u + (u32)past * 16384u + (u32)q * 4096u,
                                        A, 4096u, full, polA);
                        }
                        if (++past == 3) { past = 0; palap++; }
                    }
                }
            } else {
                // ---- 8 compute warps ----
                float acc[2][4][4];
                #pragma unroll
                for (int m = 0; m < 2; m++)
                    #pragma unroll
                    for (int tt = 0; tt < 4; tt++)
                        #pragma unroll
                        for (int r = 0; r < 4; r++) acc[m][tt][r] = 0.f;

                for (int i = 0; i < nst; i++) {
                    mbar_wait(mbFW + 8 * cst, (u32)(clap & 1));
                    mbar_wait(mbFA + 8 * cst, (u32)(clap & 1));
                    #pragma unroll
                    for (int q = 0; q < 4; q++) {
                        const u32* A = sm + 24576 + cst * 4096 + q * 1024;
                        const u32* W = sm + cst * 8192 + q * 2048;
                        u32 ah[2][4], al[2][4];
                        #pragma unroll
                        for (int m = 0; m < 2; m++) {
                            const int mt = mp * 2 + m;
                            *(uint4*)ah[m] = *(const uint4*)&A[(mt * 2 + 0) * 128 + lane * 4];
                            *(uint4*)al[m] = *(const uint4*)&A[(mt * 2 + 1) * 128 + lane * 4];
                        }
                        #pragma unroll
                        for (int tt = 0; tt < 4; tt++) {
                            const int nt = nq * 4 + tt;
                            const uint4 bv = *(const uint4*)&W[nt * 128 + lane * 4];
                            u32 bh[2] = { bv.x, bv.y }, bl[2] = { bv.z, bv.w };
                            #pragma unroll
                            for (int m = 0; m < 2; m++) {
                                mma16816(acc[m][tt], ah[m], bh);
                                mma16816(acc[m][tt], ah[m], bl);
                                mma16816(acc[m][tt], al[m], bh);
                            }
                        }
                    }
                    __syncwarp();
                    if (lane == 0) { mbar_arrive(mbEW + 8 * cst); mbar_arrive(mbEA + 8 * cst); }
                    if (++cst == 3) { cst = 0; clap++; }
                }

                #pragma unroll
                for (int m = 0; m < 2; m++) {
                    const int m0 = (mp * 2 + m) * 16;
                    #pragma unroll
                    for (int tt = 0; tt < 4; tt++) {
                        const int nb = (nq * 4 + tt) * 8 + tig * 2;
                        *(float2*)&zbuf[(m0 + gid) * 128 + nb] =
                            make_float2(acc[m][tt][0], acc[m][tt][1]);
                        *(float2*)&zbuf[(m0 + gid + 8) * 128 + nb] =
                            make_float2(acc[m][tt][2], acc[m][tt][3]);
                    }
                }
            }

            if (wid < 8) {
                CBAR();   // zbuf complete across compute warps
                u32* himg = &g_hA[prCur][layer][0];
                #pragma unroll
                for (int i = 0; i < 4; i++) {
                    const int r = rowBase + i;
                    const float4 z0 = *(const float4*)&zbuf[r * 128 + hp * 8];
                    const float4 z1 = *(const float4*)&zbuf[r * 128 + hp * 8 + 4];
                    float hn2[2], cn2[2];
                    {
                        const float ig = fsig(z0.x + b42[0][0]);
                        const float fg = fsig(z0.y + b42[0][1]);
                        const float og = fsig(z0.w + b42[0][3]);
                        const float cn = fg * creg[i][0] + ig * ftanh(z0.z + b42[0][2]);
                        hn2[0] = og * ftanh(cn); cn2[0] = cn; creg[i][0] = cn;
                    }
                    {
                        const float ig = fsig(z1.x + b42[1][0]);
                        const float fg = fsig(z1.y + b42[1][1]);
                        const float og = fsig(z1.w + b42[1][3]);
                        const float cn = fg * creg[i][1] + ig * ftanh(z1.z + b42[1][2]);
                        hn2[1] = og * ftanh(cn); cn2[1] = cn; creg[i][1] = cn;
                    }
                    const int rl = r & 15, mtr = r >> 4;
                    const int word = ((rl & 7) * 4 + tigk) * 4 + ((rl >> 3) | (regk << 1));
                    const __nv_bfloat16 h0 = __float2bfloat16(hn2[0]);
                    const __nv_bfloat16 h1 = __float2bfloat16(hn2[1]);
                    const u32 whi = (u32)((__nv_bfloat16_raw)h0).x |
                                    ((u32)((__nv_bfloat16_raw)h1).x << 16);
                    const u32 wlo = (u32)((__nv_bfloat16_raw)__float2bfloat16(
                                        hn2[0] - __bfloat162float(h0))).x |
                                    ((u32)((__nv_bfloat16_raw)__float2bfloat16(
                                        hn2[1] - __bfloat162float(h1))).x << 16);
                    himg[kchunk * 1024 + (mtr * 2 + 0) * 128 + word] = whi;
                    himg[kchunk * 1024 + (mtr * 2 + 1) * 128 + word] = wlo;
                    if (layer == 3)
                        __stcs((float2*)&out[(size_t)s * BH_ + r * 1024 + hcol0],
                               make_float2(hn2[0], hn2[1]));
                    if (s == 511) {
                        __stcs((float2*)&out[HS_ + (size_t)layer * BH_ + r * 1024 + hcol0],
                               make_float2(hn2[0], hn2[1]));
                        __stcs((float2*)&out[HS_ + 262144ull + (size_t)layer * BH_ + r * 1024 + hcol0],
                               make_float2(cn2[0], cn2[1]));
                    }
                }
            }
        }
        if (wid < 8 && w < 512 + 2) grid_sync_c();
    }
}

extern "C" void kernel_launch(void* const* d_in, const int* in_sizes, int n_in,
                              void* d_out, int out_size)
{
    const float* x   = (const float*)d_in[0];
    const float* Wx0 = (const float*)d_in[1];
    const float* Wh0 = (const float*)d_in[2];
    const float* b0  = (const float*)d_in[3];
    const float* Wxr = (const float*)d_in[4];
    const float* Whr = (const float*)d_in[5];
    const float* br  = (const float*)d_in[6];
    float* out = (float*)d_out;

    prep_w<<<15360, 256>>>(Wx0, Wh0, Wxr, Whr);
    prep_x<<<16384, 256>>>(x);   // also zeroes g_hA + g_sync (replay-safe)

    cudaFuncSetAttribute(lstm_persist, cudaFuncAttributeMaxDynamicSharedMemorySize, SMEM_DYN);
    lstm_persist<<<NCTA, NTHR, SMEM_DYN>>>(b0, br, out);
}

// round 15
// speedup vs baseline: 1.0295x; 1.0295x over previous
#include <cuda_runtime.h>
#include <cuda_bf16.h>
#include <math.h>
#include <cstdint>

typedef unsigned int u32;
typedef unsigned long long ull;

#define NCTA 128
#define NTHR 320          // 8 compute + 1 W-producer + 1 A-producer warps
#define HS_  33554432ull
#define BH_  65536
// W-ring 3x32KB + A-ring 3x16KB + 32KB zbuf + barriers
#define SMEM_DYN 180352

__device__ __align__(16) u32 g_W[31457280];      // weight images, B-fragment order
__device__ __align__(16) u32 g_x[16777216];      // x images, A-fragment order
__device__ __align__(16) u32 g_hA[2][4][65536];  // h images [parity][layer]
__device__ unsigned g_sync[2];                   // [0]=count, [1]=generation (never reset; all uses relative)

__device__ __forceinline__ u32 sm_u32(const void* p) {
    u32 a;
    asm("{.reg .u64 t; cvta.to.shared.u64 t, %1; cvt.u32.u64 %0, t;}" : "=r"(a) : "l"(p));
    return a;
}
__device__ __forceinline__ void bulk_cp(u32 dst, const void* src, u32 bytes, u32 mbar) {
    asm volatile("cp.async.bulk.shared::cluster.global.mbarrier::complete_tx::bytes "
                 "[%0], [%1], %2, [%3];" :: "r"(dst), "l"(src), "r"(bytes), "r"(mbar) : "memory");
}
__device__ __forceinline__ void mbar_init(u32 a, u32 c) {
    asm volatile("mbarrier.init.shared.b64 [%0], %1;" :: "r"(a), "r"(c) : "memory");
}
__device__ __forceinline__ void mbar_expect(u32 a, u32 tx) {
    asm volatile("mbarrier.arrive.expect_tx.shared.b64 _, [%0], %1;" :: "r"(a), "r"(tx) : "memory");
}
__device__ __forceinline__ void mbar_arrive(u32 a) {
    asm volatile("mbarrier.arrive.shared.b64 _, [%0];" :: "r"(a) : "memory");
}
__device__ __forceinline__ void mbar_wait(u32 a, u32 ph) {
    u32 done = 0;
    while (!done)
        asm volatile("{.reg .pred p; mbarrier.try_wait.parity.acquire.cta.shared::cta.b64 "
                     "p, [%1], %2, 0x989680; selp.b32 %0,1,0,p;}"
                     : "=r"(done) : "r"(a), "r"(ph) : "memory");
}
__device__ __forceinline__ void mma16816(float* c, const u32* a, const u32* b) {
    asm("mma.sync.aligned.m16n8k16.row.col.f32.bf16.bf16.f32 "
        "{%0,%1,%2,%3}, {%4,%5,%6,%7}, {%8,%9}, {%0,%1,%2,%3};"
        : "+f"(c[0]), "+f"(c[1]), "+f"(c[2]), "+f"(c[3])
        : "r"(a[0]), "r"(a[1]), "r"(a[2]), "r"(a[3]), "r"(b[0]), "r"(b[1]));
}
__device__ __forceinline__ u32 pack2(float v0, float v1, bool lo) {
    __nv_bfloat16 h0 = __float2bfloat16(v0), h1 = __float2bfloat16(v1);
    if (lo) {
        h0 = __float2bfloat16(v0 - __bfloat162float(h0));
        h1 = __float2bfloat16(v1 - __bfloat162float(h1));
    }
    u32 u0 = ((__nv_bfloat16_raw)h0).x, u1 = ((__nv_bfloat16_raw)h1).x;
    return u0 | (u1 << 16);
}
__device__ __forceinline__ float fsig(float x) {
    return __fdividef(1.f, 1.f + __expf(-x));
}
__device__ __forceinline__ float ftanh(float x) {
    const float e = __expf(-2.f * x);
    return __fdividef(1.f - e, 1.f + e);
}
#define CBAR() asm volatile("bar.sync 1, 256;" ::: "memory")
#define GEN()  (*(volatile unsigned*)&g_sync[1])

// grid barrier over compute warps only (t < 256); producers observe GEN().
__device__ __forceinline__ void grid_sync_c() {
    CBAR();
    if (threadIdx.x == 0) {
        __threadfence();
        unsigned gen = GEN();
        if (atomicAdd(&g_sync[0], 1u) == NCTA - 1u) {
            g_sync[0] = 0;
            __threadfence();
            GEN() = gen + 1u;
        } else {
            while (GEN() == gen) __nanosleep(32);
        }
        __threadfence();
    }
    CBAR();
}

__global__ void __launch_bounds__(NTHR, 1)
lstm_persist(const float* __restrict__ x,
             const float* __restrict__ Wx0, const float* __restrict__ Wh0,
             const float* __restrict__ b0,
             const float* __restrict__ Wxr, const float* __restrict__ Whr,
             const float* __restrict__ br,
             float* __restrict__ out)
{
    extern __shared__ __align__(16) u32 sm[];
    // layout (u32): W-ring [0,24576), A-ring [24576,36864), zbuf [36864,45056)
    float* zbuf = (float*)(sm + 36864);
    const u32 smb = sm_u32(sm);
    const u32 mbF = smb + 180224u;    // merged full[3], arrive count 2
    const u32 mbEW = smb + 180248u;   // W empty[3]
    const u32 mbEA = smb + 180272u;   // A empty[3]
    __shared__ unsigned s_g0;

    const int t = threadIdx.x, lane = t & 31, wid = t >> 5;

    // ================= PROLOGUE: image prep (grid-strided, all warps) =======
    // zero h images
    for (int z = blockIdx.x * NTHR + t; z < 524288; z += NCTA * NTHR)
        ((u32*)g_hA)[z] = 0;
    // weight images, B-fragment order: [nt][lane][slot{bh0,bh1,bl0,bl1}]
    for (int b = blockIdx.x; b < 15360; b += NCTA) {
        int l, nblk, c;
        if (b < 3072) { l = 0; nblk = b / 96; c = b % 96; }
        else { int r = b - 3072; l = 1 + r / 4096; r %= 4096; nblk = r / 128; c = r % 128; }
        const int ntA_ = (l == 0) ? 32 : 64;
        const float* Wsrc; int kb;
        if (c < ntA_) { Wsrc = (l == 0) ? Wx0 : Wxr + (size_t)(l - 1) * 4194304; kb = c * 16; }
        else          { Wsrc = (l == 0) ? Wh0 : Whr + (size_t)(l - 1) * 4194304; kb = (c - ntA_) * 16; }
        u32* dst = g_W + (size_t)b * 2048;
        for (int gw = t; gw < 2048; gw += NTHR) {
            const int nt = gw >> 7, rem = gw & 127, ln = rem >> 2, slot = rem & 3;
            const int hl = slot >> 1, reg = slot & 1;
            const int n = nt * 8 + (ln >> 2);
            const int zc = (n & 3) * 1024 + nblk * 32 + (n >> 2);
            const int k = kb + (ln & 3) * 2 + reg * 8;
            dst[gw] = pack2(__ldg(&Wsrc[(size_t)k * 4096 + zc]),
                            __ldg(&Wsrc[(size_t)(k + 1) * 4096 + zc]), hl != 0);
        }
    }
    // x images, A-fragment order
    for (int bb = blockIdx.x; bb < 16384; bb += NCTA) {
        const int s_ = bb >> 5, c_ = bb & 31;
        u32* dst = g_x + (size_t)bb * 1024;
        for (int gw = t; gw < 1024; gw += NTHR) {
            const int mt = gw >> 8, rem = gw & 255, hl = rem >> 7, ww = rem & 127;
            const int ln = ww >> 2, reg = ww & 3;
            const int row = mt * 16 + (ln >> 2) + (reg & 1) * 8;
            const int k   = c_ * 16 + (ln & 3) * 2 + (reg >> 1) * 8;
            const float* p = x + (size_t)s_ * 32768 + row * 512 + k;
            dst[gw] = pack2(__ldg(p), __ldg(p + 1), hl != 0);
        }
    }
    // mbarrier init + prologue grid barrier (all 320 threads wait; t0 arrives)
    __syncthreads();
    if (t == 0) {
        #pragma unroll
        for (int i = 0; i < 3; i++) {
            mbar_init(mbF + 8 * i, 2);      // 2 producers expect_tx per phase
            mbar_init(mbEW + 8 * i, 8);
            mbar_init(mbEA + 8 * i, 8);
        }
        asm volatile("fence.proxy.async;" ::: "memory");
        __threadfence();
        unsigned gen = GEN();
        if (atomicAdd(&g_sync[0], 1u) == NCTA - 1u) {
            g_sync[0] = 0;
            __threadfence();
            GEN() = gen + 1u;
        } else {
            while (GEN() == gen) __nanosleep(64);
        }
        __threadfence();
        s_g0 = gen + 1u;   // globally unique post-barrier generation
    }
    __syncthreads();
    const unsigned g0 = s_g0;

    // ================= MAIN WAVEFRONT LOOP ==================================
    const int layer = blockIdx.x >> 5, nblk = blockIdx.x & 31;
    const int mp = wid & 1, nq = wid >> 1;       // warp tile: 2 m-tiles x 4 n-tiles
    const int gid = lane >> 2, tig = lane & 3;
    const int ntA = (layer == 0) ? 32 : 64;
    const int nst = (ntA + 64) >> 2;             // stages per wave: 24 or 32
    const size_t wbase = (layer == 0) ? (size_t)nblk * 96
                                      : 3072 + ((size_t)(layer - 1) * 32 + nblk) * 128;
    const float* bias = (layer == 0) ? b0 : br + (size_t)(layer - 1) * 4096;

    // epilogue ownership: 4 rows x 2 adjacent hcols (t < 256 only)
    const int hp = t & 15;
    const int rowBase = (t >> 4) * 4;
    const int hcol0 = nblk * 32 + hp * 2;
    float b42[2][4];
    #pragma unroll
    for (int cc = 0; cc < 2; cc++)
        #pragma unroll
        for (int g = 0; g < 4; g++)
            b42[cc][g] = __ldg(bias + g * 1024 + ((hcol0 + cc) & 1023));
    float creg[4][2];
    #pragma unroll
    for (int i = 0; i < 4; i++) { creg[i][0] = 0.f; creg[i][1] = 0.f; }

    const int kchunk = hcol0 >> 4;
    const int kl = hcol0 & 15;
    const int tigk = (kl >> 1) & 3, regk = kl >> 3;

    // ring cursors
    int pwst = 0, pwlap = 0;   // W-producer
    int past = 0, palap = 0;   // A-producer
    int cst = 0,  clap = 0;    // consumer

    for (int w = 0; w < 512 + 3; w++) {
        const int s = w - layer;
        if (s >= 0 && s < 512) {
            const int prPrev = (w & 1) ^ 1, prCur = w & 1;

            if (wid == 8) {
                // ---- W producer: free-running, ring-backpressured only ----
                if (lane == 0) {
                    for (int i = 0; i < nst; i++) {
                        if (pwlap > 0) mbar_wait(mbEW + 8 * pwst, (u32)((pwlap - 1) & 1));
                        const u32 full = mbF + 8 * pwst;
                        mbar_expect(full, 32768u);
                        #pragma unroll
                        for (int q = 0; q < 4; q++)
                            bulk_cp(smb + (u32)pwst * 32768u + (u32)q * 8192u,
                                    g_W + (wbase + i * 4 + q) * 2048, 8192u, full);
                        if (++pwst == 3) { pwst = 0; pwlap++; }
                    }
                }
            } else if (wid == 9) {
                // ---- A producer: gated by grid-barrier generation (relative) ----
                if (lane == 0) {
                    if (w >= 1) {
                        while ((unsigned)(GEN() - g0) < (unsigned)w) __nanosleep(32);
                        __threadfence();
                    }
                    const u32* a0 = (layer == 0) ? g_x + (size_t)s * 32768
                                                 : &g_hA[prPrev][layer - 1][0];
                    const u32* a1 = &g_hA[prPrev][layer][0];
                    for (int i = 0; i < nst; i++) {
                        if (palap > 0) mbar_wait(mbEA + 8 * past, (u32)((palap - 1) & 1));
                        const u32 full = mbF + 8 * past;
                        mbar_expect(full, 16384u);
                        #pragma unroll
                        for (int q = 0; q < 4; q++) {
                            const int c = i * 4 + q;
                            const u32* A = (c < ntA) ? a0 + (size_t)c * 1024
                                                     : a1 + (size_t)(c - ntA) * 1024;
                            bulk_cp(smb + 98304u + (u32)past * 16384u + (u32)q * 4096u,
                                    A, 4096u, full);
                        }
                        if (++past == 3) { past = 0; palap++; }
                    }
                }
            } else {
                // ---- 8 compute warps ----
                float acc[2][4][4];
                #pragma unroll
                for (int m = 0; m < 2; m++)
                    #pragma unroll
                    for (int tt = 0; tt < 4; tt++)
                        #pragma unroll
                        for (int r = 0; r < 4; r++) acc[m][tt][r] = 0.f;

                for (int i = 0; i < nst; i++) {
                    mbar_wait(mbF + 8 * cst, (u32)(clap & 1));
                    #pragma unroll
                    for (int q = 0; q < 4; q++) {
                        const u32* A = sm + 24576 + cst * 4096 + q * 1024;
                        const u32* W = sm + cst * 8192 + q * 2048;
                        u32 ah[2][4], al[2][4];
                        #pragma unroll
                        for (int m = 0; m < 2; m++) {
                            const int mt = mp * 2 + m;
                            *(uint4*)ah[m] = *(const uint4*)&A[(mt * 2 + 0) * 128 + lane * 4];
                            *(uint4*)al[m] = *(const uint4*)&A[(mt * 2 + 1) * 128 + lane * 4];
                        }
                        #pragma unroll
                        for (int tt = 0; tt < 4; tt++) {
                            const int nt = nq * 4 + tt;
                            const uint4 bv = *(const uint4*)&W[nt * 128 + lane * 4];
                            u32 bh[2] = { bv.x, bv.y }, bl[2] = { bv.z, bv.w };
                            #pragma unroll
                            for (int m = 0; m < 2; m++) {
                                mma16816(acc[m][tt], ah[m], bh);
                                mma16816(acc[m][tt], ah[m], bl);
                                mma16816(acc[m][tt], al[m], bh);
                            }
                        }
                    }
                    __syncwarp();
                    if (lane == 0) { mbar_arrive(mbEW + 8 * cst); mbar_arrive(mbEA + 8 * cst); }
                    if (++cst == 3) { cst = 0; clap++; }
                }

                #pragma unroll
                for (int m = 0; m < 2; m++) {
                    const int m0 = (mp * 2 + m) * 16;
                    #pragma unroll
                    for (int tt = 0; tt < 4; tt++) {
                        const int nb = (nq * 4 + tt) * 8 + tig * 2;
                        *(float2*)&zbuf[(m0 + gid) * 128 + nb] =
                            make_float2(acc[m][tt][0], acc[m][tt][1]);
                        *(float2*)&zbuf[(m0 + gid + 8) * 128 + nb] =
                            make_float2(acc[m][tt][2], acc[m][tt][3]);
                    }
                }
            }

            if (wid < 8) {
                CBAR();   // zbuf complete across compute warps
                u32* himg = &g_hA[prCur][layer][0];
                #pragma unroll
                for (int i = 0; i < 4; i++) {
                    const int r = rowBase + i;
                    const float4 z0 = *(const float4*)&zbuf[r * 128 + hp * 8];
                    const float4 z1 = *(const float4*)&zbuf[r * 128 + hp * 8 + 4];
                    float hn2[2], cn2[2];
                    {
                        const float ig = fsig(z0.x + b42[0][0]);
                        const float fg = fsig(z0.y + b42[0][1]);
                        const float og = fsig(z0.w + b42[0][3]);
                        const float cn = fg * creg[i][0] + ig * ftanh(z0.z + b42[0][2]);
                        hn2[0] = og * ftanh(cn); cn2[0] = cn; creg[i][0] = cn;
                    }
                    {
                        const float ig = fsig(z1.x + b42[1][0]);
                        const float fg = fsig(z1.y + b42[1][1]);
                        const float og = fsig(z1.w + b42[1][3]);
                        const float cn = fg * creg[i][1] + ig * ftanh(z1.z + b42[1][2]);
                        hn2[1] = og * ftanh(cn); cn2[1] = cn; creg[i][1] = cn;
                    }
                    const int rl = r & 15, mtr = r >> 4;
                    const int word = ((rl & 7) * 4 + tigk) * 4 + ((rl >> 3) | (regk << 1));
                    const __nv_bfloat16 h0 = __float2bfloat16(hn2[0]);
                    const __nv_bfloat16 h1 = __float2bfloat16(hn2[1]);
                    const u32 whi = (u32)((__nv_bfloat16_raw)h0).x |
                                    ((u32)((__nv_bfloat16_raw)h1).x << 16);
                    const u32 wlo = (u32)((__nv_bfloat16_raw)__float2bfloat16(
                                        hn2[0] - __bfloat162float(h0))).x |
                                    ((u32)((__nv_bfloat16_raw)__float2bfloat16(
                                        hn2[1] - __bfloat162float(h1))).x << 16);
                    himg[kchunk * 1024 + (mtr * 2 + 0) * 128 + word] = whi;
                    himg[kchunk * 1024 + (mtr * 2 + 1) * 128 + word] = wlo;
                    if (layer == 3)
                        *(float2*)&out[(size_t)s * BH_ + r * 1024 + hcol0] =
                            make_float2(hn2[0], hn2[1]);
                    if (s == 511) {
                        *(float2*)&out[HS_ + (size_t)layer * BH_ + r * 1024 + hcol0] =
                            make_float2(hn2[0], hn2[1]);
                        *(float2*)&out[HS_ + 262144ull + (size_t)layer * BH_ + r * 1024 + hcol0] =
                            make_float2(cn2[0], cn2[1]);
                    }
                }
            }
        }
        if (wid < 8 && w < 512 + 2) grid_sync_c();
    }
}

extern "C" void kernel_launch(void* const* d_in, const int* in_sizes, int n_in,
                              void* d_out, int out_size)
{
    const float* x   = (const float*)d_in[0];
    const float* Wx0 = (const float*)d_in[1];
    const float* Wh0 = (const float*)d_in[2];
    const float* b0  = (const float*)d_in[3];
    const float* Wxr = (const float*)d_in[4];
    const float* Whr = (const float*)d_in[5];
    const float* br  = (const float*)d_in[6];
    float* out = (float*)d_out;

    cudaFuncSetAttribute(lstm_persist, cudaFuncAttributeMaxDynamicSharedMemorySize, SMEM_DYN);
    lstm_persist<<<NCTA, NTHR, SMEM_DYN>>>(x, Wx0, Wh0, b0, Wxr, Whr, br, out);
}

// round 16
// speedup vs baseline: 1.3836x; 1.3439x over previous
#include <cuda_runtime.h>
#include <cuda_fp16.h>
#include <math.h>
#include <cstdint>

typedef unsigned int u32;
typedef unsigned long long ull;

#define NCTA 128
#define NTHR 320          // 8 compute + 1 W-producer + 1 A-producer warps
#define HS_  33554432ull
#define BH_  65536
// W-ring 3x16KB + A-ring 3x16KB + 32KB zbuf + barriers
#define SMEM_DYN 131200

__device__ __align__(16) u32 g_W[15728640];      // fp16 weight images (60MB), B-fragment order
__device__ __align__(16) u32 g_x[16777216];      // fp16 hi/lo x images, A-fragment order
__device__ __align__(16) u32 g_hA[2][4][65536];  // fp16 hi/lo h images [parity][layer]
__device__ unsigned g_sync[2];                   // [0]=count, [1]=generation (relative use only)

__device__ __forceinline__ u32 sm_u32(const void* p) {
    u32 a;
    asm("{.reg .u64 t; cvta.to.shared.u64 t, %1; cvt.u32.u64 %0, t;}" : "=r"(a) : "l"(p));
    return a;
}
__device__ __forceinline__ void bulk_cp(u32 dst, const void* src, u32 bytes, u32 mbar) {
    asm volatile("cp.async.bulk.shared::cluster.global.mbarrier::complete_tx::bytes "
                 "[%0], [%1], %2, [%3];" :: "r"(dst), "l"(src), "r"(bytes), "r"(mbar) : "memory");
}
__device__ __forceinline__ void mbar_init(u32 a, u32 c) {
    asm volatile("mbarrier.init.shared.b64 [%0], %1;" :: "r"(a), "r"(c) : "memory");
}
__device__ __forceinline__ void mbar_expect(u32 a, u32 tx) {
    asm volatile("mbarrier.arrive.expect_tx.shared.b64 _, [%0], %1;" :: "r"(a), "r"(tx) : "memory");
}
__device__ __forceinline__ void mbar_arrive(u32 a) {
    asm volatile("mbarrier.arrive.shared.b64 _, [%0];" :: "r"(a) : "memory");
}
__device__ __forceinline__ void mbar_wait(u32 a, u32 ph) {
    u32 done = 0;
    while (!done)
        asm volatile("{.reg .pred p; mbarrier.try_wait.parity.acquire.cta.shared::cta.b64 "
                     "p, [%1], %2, 0x989680; selp.b32 %0,1,0,p;}"
                     : "=r"(done) : "r"(a), "r"(ph) : "memory");
}
// f16 x f16 -> f32 MMA
__device__ __forceinline__ void mma16816(float* c, const u32* a, const u32* b) {
    asm("mma.sync.aligned.m16n8k16.row.col.f32.f16.f16.f32 "
        "{%0,%1,%2,%3}, {%4,%5,%6,%7}, {%8,%9}, {%0,%1,%2,%3};"
        : "+f"(c[0]), "+f"(c[1]), "+f"(c[2]), "+f"(c[3])
        : "r"(a[0]), "r"(a[1]), "r"(a[2]), "r"(a[3]), "r"(b[0]), "r"(b[1]));
}
__device__ __forceinline__ u32 pack2h(float v0, float v1, bool lo) {
    __half h0 = __float2half_rn(v0), h1 = __float2half_rn(v1);
    if (lo) {
        h0 = __float2half_rn(v0 - __half2float(h0));
        h1 = __float2half_rn(v1 - __half2float(h1));
    }
    u32 u0 = (u32)__half_as_ushort(h0), u1 = (u32)__half_as_ushort(h1);
    return u0 | (u1 << 16);
}
__device__ __forceinline__ float fsig(float x) {
    return __fdividef(1.f, 1.f + __expf(-x));
}
__device__ __forceinline__ float ftanh(float x) {
    const float e = __expf(-2.f * x);
    return __fdividef(1.f - e, 1.f + e);
}
#define CBAR() asm volatile("bar.sync 1, 256;" ::: "memory")
#define GEN()  (*(volatile unsigned*)&g_sync[1])

// grid barrier over compute warps only (t < 256); producers observe GEN().
__device__ __forceinline__ void grid_sync_c() {
    CBAR();
    if (threadIdx.x == 0) {
        __threadfence();
        unsigned gen = GEN();
        if (atomicAdd(&g_sync[0], 1u) == NCTA - 1u) {
            g_sync[0] = 0;
            __threadfence();
            GEN() = gen + 1u;
        } else {
            while (GEN() == gen) __nanosleep(32);
        }
        __threadfence();
    }
    CBAR();
}

__global__ void __launch_bounds__(NTHR, 1)
lstm_persist(const float* __restrict__ x,
             const float* __restrict__ Wx0, const float* __restrict__ Wh0,
             const float* __restrict__ b0,
             const float* __restrict__ Wxr, const float* __restrict__ Whr,
             const float* __restrict__ br,
             float* __restrict__ out)
{
    extern __shared__ __align__(16) u32 sm[];
    // layout (u32): W-ring [0,12288), A-ring [12288,24576), zbuf [24576,32768)
    float* zbuf = (float*)(sm + 24576);
    const u32 smb = sm_u32(sm);
    const u32 mbF  = smb + 131072u;   // merged full[3], arrive count 2
    const u32 mbEW = smb + 131096u;   // W empty[3]
    const u32 mbEA = smb + 131120u;   // A empty[3]
    __shared__ unsigned s_g0;

    const int t = threadIdx.x, lane = t & 31, wid = t >> 5;

    // ================= PROLOGUE: image prep (grid-strided, all warps) =======
    for (int z = blockIdx.x * NTHR + t; z < 524288; z += NCTA * NTHR)
        ((u32*)g_hA)[z] = 0;
    // weight images, fp16 B-fragment order: [nt][lane][slot{b0,b1}]
    for (int b = blockIdx.x; b < 15360; b += NCTA) {
        int l, nblk, c;
        if (b < 3072) { l = 0; nblk = b / 96; c = b % 96; }
        else { int r = b - 3072; l = 1 + r / 4096; r %= 4096; nblk = r / 128; c = r % 128; }
        const int ntA_ = (l == 0) ? 32 : 64;
        const float* Wsrc; int kb;
        if (c < ntA_) { Wsrc = (l == 0) ? Wx0 : Wxr + (size_t)(l - 1) * 4194304; kb = c * 16; }
        else          { Wsrc = (l == 0) ? Wh0 : Whr + (size_t)(l - 1) * 4194304; kb = (c - ntA_) * 16; }
        u32* dst = g_W + (size_t)b * 1024;
        for (int gw = t; gw < 1024; gw += NTHR) {
            const int nt = gw >> 6, rem = gw & 63, ln = rem >> 1, reg = rem & 1;
            const int n = nt * 8 + (ln >> 2);
            const int zc = (n & 3) * 1024 + nblk * 32 + (n >> 2);
            const int k = kb + (ln & 3) * 2 + reg * 8;
            dst[gw] = pack2h(__ldg(&Wsrc[(size_t)k * 4096 + zc]),
                             __ldg(&Wsrc[(size_t)(k + 1) * 4096 + zc]), false);
        }
    }
    // x images, fp16 hi/lo A-fragment order
    for (int bb = blockIdx.x; bb < 16384; bb += NCTA) {
        const int s_ = bb >> 5, c_ = bb & 31;
        u32* dst = g_x + (size_t)bb * 1024;
        for (int gw = t; gw < 1024; gw += NTHR) {
            const int mt = gw >> 8, rem = gw & 255, hl = rem >> 7, ww = rem & 127;
            const int ln = ww >> 2, reg = ww & 3;
            const int row = mt * 16 + (ln >> 2) + (reg & 1) * 8;
            const int k   = c_ * 16 + (ln & 3) * 2 + (reg >> 1) * 8;
            const float* p = x + (size_t)s_ * 32768 + row * 512 + k;
            dst[gw] = pack2h(__ldg(p), __ldg(p + 1), hl != 0);
        }
    }
    __syncthreads();
    if (t == 0) {
        #pragma unroll
        for (int i = 0; i < 3; i++) {
            mbar_init(mbF + 8 * i, 2);      // W + A producers expect_tx per phase
            mbar_init(mbEW + 8 * i, 8);
            mbar_init(mbEA + 8 * i, 8);
        }
        asm volatile("fence.proxy.async;" ::: "memory");
        __threadfence();
        unsigned gen = GEN();
        if (atomicAdd(&g_sync[0], 1u) == NCTA - 1u) {
            g_sync[0] = 0;
            __threadfence();
            GEN() = gen + 1u;
        } else {
            while (GEN() == gen) __nanosleep(64);
        }
        __threadfence();
        s_g0 = gen + 1u;
    }
    __syncthreads();
    const unsigned g0 = s_g0;

    // ================= MAIN WAVEFRONT LOOP ==================================
    const int layer = blockIdx.x >> 5, nblk = blockIdx.x & 31;
    const int mp = wid & 1, nq = wid >> 1;       // warp tile: 2 m-tiles x 4 n-tiles
    const int gid = lane >> 2, tig = lane & 3;
    const int ntA = (layer == 0) ? 32 : 64;
    const int nst = (ntA + 64) >> 2;             // stages per wave: 24 or 32
    const size_t wbase = (layer == 0) ? (size_t)nblk * 96
                                      : 3072 + ((size_t)(layer - 1) * 32 + nblk) * 128;
    const float* bias = (layer == 0) ? b0 : br + (size_t)(layer - 1) * 4096;

    const int hp = t & 15;
    const int rowBase = (t >> 4) * 4;
    const int hcol0 = nblk * 32 + hp * 2;
    float b42[2][4];
    #pragma unroll
    for (int cc = 0; cc < 2; cc++)
        #pragma unroll
        for (int g = 0; g < 4; g++)
            b42[cc][g] = __ldg(bias + g * 1024 + ((hcol0 + cc) & 1023));
    float creg[4][2];
    #pragma unroll
    for (int i = 0; i < 4; i++) { creg[i][0] = 0.f; creg[i][1] = 0.f; }

    const int kchunk = hcol0 >> 4;
    const int kl = hcol0 & 15;
    const int tigk = (kl >> 1) & 3, regk = kl >> 3;

    int pwst = 0, pwlap = 0;   // W-producer
    int past = 0, palap = 0;   // A-producer
    int cst = 0,  clap = 0;    // consumer

    for (int w = 0; w < 512 + 3; w++) {
        const int s = w - layer;
        if (s >= 0 && s < 512) {
            const int prPrev = (w & 1) ^ 1, prCur = w & 1;

            if (wid == 8) {
                // ---- W producer: free-running, ring-backpressured only ----
                if (lane == 0) {
                    for (int i = 0; i < nst; i++) {
                        if (pwlap > 0) mbar_wait(mbEW + 8 * pwst, (u32)((pwlap - 1) & 1));
                        const u32 full = mbF + 8 * pwst;
                        mbar_expect(full, 16384u);
                        #pragma unroll
                        for (int q = 0; q < 4; q++)
                            bulk_cp(smb + (u32)pwst * 16384u + (u32)q * 4096u,
                                    g_W + (wbase + i * 4 + q) * 1024, 4096u, full);
                        if (++pwst == 3) { pwst = 0; pwlap++; }
                    }
                }
            } else if (wid == 9) {
                // ---- A producer: gated by grid-barrier generation (relative) ----
                if (lane == 0) {
                    if (w >= 1) {
                        while ((unsigned)(GEN() - g0) < (unsigned)w) __nanosleep(32);
                        __threadfence();
                    }
                    const u32* a0 = (layer == 0) ? g_x + (size_t)s * 32768
                                                 : &g_hA[prPrev][layer - 1][0];
                    const u32* a1 = &g_hA[prPrev][layer][0];
                    for (int i = 0; i < nst; i++) {
                        if (palap > 0) mbar_wait(mbEA + 8 * past, (u32)((palap - 1) & 1));
                        const u32 full = mbF + 8 * past;
                        mbar_expect(full, 16384u);
                        #pragma unroll
                        for (int q = 0; q < 4; q++) {
                            const int c = i * 4 + q;
                            const u32* A = (c < ntA) ? a0 + (size_t)c * 1024
                                                     : a1 + (size_t)(c - ntA) * 1024;
                            bulk_cp(smb + 49152u + (u32)past * 16384u + (u32)q * 4096u,
                                    A, 4096u, full);
                        }
                        if (++past == 3) { past = 0; palap++; }
                    }
                }
            } else {
                // ---- 8 compute warps ----
                float acc[2][4][4];
                #pragma unroll
                for (int m = 0; m < 2; m++)
                    #pragma unroll
                    for (int tt = 0; tt < 4; tt++)
                        #pragma unroll
                        for (int r = 0; r < 4; r++) acc[m][tt][r] = 0.f;

                for (int i = 0; i < nst; i++) {
                    mbar_wait(mbF + 8 * cst, (u32)(clap & 1));
                    #pragma unroll
                    for (int q = 0; q < 4; q++) {
                        const u32* A = sm + 12288 + cst * 4096 + q * 1024;
                        const u32* W = sm + cst * 4096 + q * 1024;
                        u32 ah[2][4], al[2][4];
                        #pragma unroll
                        for (int m = 0; m < 2; m++) {
                            const int mt = mp * 2 + m;
                            *(uint4*)ah[m] = *(const uint4*)&A[(mt * 2 + 0) * 128 + lane * 4];
                            *(uint4*)al[m] = *(const uint4*)&A[(mt * 2 + 1) * 128 + lane * 4];
                        }
                        #pragma unroll
                        for (int tt = 0; tt < 4; tt++) {
                            const int nt = nq * 4 + tt;
                            u32 bb[2];
                            *(ull*)bb = *(const ull*)&W[nt * 64 + lane * 2];
                            #pragma unroll
                            for (int m = 0; m < 2; m++) {
                                mma16816(acc[m][tt], ah[m], bb);
                                mma16816(acc[m][tt], al[m], bb);
                            }
                        }
                    }
                    __syncwarp();
                    if (lane == 0) { mbar_arrive(mbEW + 8 * cst); mbar_arrive(mbEA + 8 * cst); }
                    if (++cst == 3) { cst = 0; clap++; }
                }

                #pragma unroll
                for (int m = 0; m < 2; m++) {
                    const int m0 = (mp * 2 + m) * 16;
                    #pragma unroll
                    for (int tt = 0; tt < 4; tt++) {
                        const int nb = (nq * 4 + tt) * 8 + tig * 2;
                        *(float2*)&zbuf[(m0 + gid) * 128 + nb] =
                            make_float2(acc[m][tt][0], acc[m][tt][1]);
                        *(float2*)&zbuf[(m0 + gid + 8) * 128 + nb] =
                            make_float2(acc[m][tt][2], acc[m][tt][3]);
                    }
                }
            }

            if (wid < 8) {
                CBAR();   // zbuf complete across compute warps
                u32* himg = &g_hA[prCur][layer][0];
                #pragma unroll
                for (int i = 0; i < 4; i++) {
                    const int r = rowBase + i;
                    const float4 z0 = *(const float4*)&zbuf[r * 128 + hp * 8];
                    const float4 z1 = *(const float4*)&zbuf[r * 128 + hp * 8 + 4];
                    float hn2[2], cn2[2];
                    {
                        const float ig = fsig(z0.x + b42[0][0]);
                        const float fg = fsig(z0.y + b42[0][1]);
                        const float og = fsig(z0.w + b42[0][3]);
                        const float cn = fg * creg[i][0] + ig * ftanh(z0.z + b42[0][2]);
                        hn2[0] = og * ftanh(cn); cn2[0] = cn; creg[i][0] = cn;
                    }
                    {
                        const float ig = fsig(z1.x + b42[1][0]);
                        const float fg = fsig(z1.y + b42[1][1]);
                        const float og = fsig(z1.w + b42[1][3]);
                        const float cn = fg * creg[i][1] + ig * ftanh(z1.z + b42[1][2]);
                        hn2[1] = og * ftanh(cn); cn2[1] = cn; creg[i][1] = cn;
                    }
                    const int rl = r & 15, mtr = r >> 4;
                    const int word = ((rl & 7) * 4 + tigk) * 4 + ((rl >> 3) | (regk << 1));
                    const u32 whi = pack2h(hn2[0], hn2[1], false);
                    const u32 wlo = pack2h(hn2[0], hn2[1], true);
                    himg[kchunk * 1024 + (mtr * 2 + 0) * 128 + word] = whi;
                    himg[kchunk * 1024 + (mtr * 2 + 1) * 128 + word] = wlo;
                    if (layer == 3)
                        *(float2*)&out[(size_t)s * BH_ + r * 1024 + hcol0] =
                            make_float2(hn2[0], hn2[1]);
                    if (s == 511) {
                        *(float2*)&out[HS_ + (size_t)layer * BH_ + r * 1024 + hcol0] =
                            make_float2(hn2[0], hn2[1]);
                        *(float2*)&out[HS_ + 262144ull + (size_t)layer * BH_ + r * 1024 + hcol0] =
                            make_float2(cn2[0], cn2[1]);
                    }
                }
            }
        }
        if (wid < 8 && w < 512 + 2) grid_sync_c();
    }
}

extern "C" void kernel_launch(void* const* d_in, const int* in_sizes, int n_in,
                              void* d_out, int out_size)
{
    const float* x   = (const float*)d_in[0];
    const float* Wx0 = (const float*)d_in[1];
    const float* Wh0 = (const float*)d_in[2];
    const float* b0  = (const float*)d_in[3];
    const float* Wxr = (const float*)d_in[4];
    const float* Whr = (const float*)d_in[5];
    const float* br  = (const float*)d_in[6];
    float* out = (float*)d_out;

    cudaFuncSetAttribute(lstm_persist, cudaFuncAttributeMaxDynamicSharedMemorySize, SMEM_DYN);
    lstm_persist<<<NCTA, NTHR, SMEM_DYN>>>(x, Wx0, Wh0, b0, Wxr, Whr, br, out);
}